// round 12
// baseline (speedup 1.0000x reference)
#include <cuda_runtime.h>
#include <math.h>
#include <stdint.h>

#define TT 2048
#define DD 2048
#define NH 16
#define NKV 4
#define HDIM 128
#define DQ 2048    // NH*HD
#define DKV 512    // NKV*HD
#define RDIM 1024  // D/2
#define EMA_L 64
#define EMA_NC 32

#define BETA 0.9f
#define ALPHA 0.1f
#define ATTN_SCALE 0.08838834764831843f  // 1/sqrt(128)
#define LOG2E 1.4426950408889634f

// ------------------- scratch -------------------
__device__ float g_l2[TT * DD];
__device__ float g_q[TT * DQ];
__device__ float g_h[TT * RDIM];
__device__ float g_fused[TT * DD];
__device__ float g_k[TT * DKV];
__device__ float g_v[TT * DKV];
__device__ float g_attn[TT * DQ];
__device__ float g_carry[EMA_NC * DD];
__device__ float g_prefix[EMA_NC * DD];
__device__ double g_invfreq[64];
// tf32-pre-rounded operand copies
__device__ float g_xr[TT * DD];
__device__ float g_wq[DD * DQ];
__device__ float g_wk[DD * DKV];
__device__ float g_wv[DD * DKV];
__device__ float g_wo[DQ * DD];
__device__ float g_wr1[DD * RDIM];

// ------------------- tf32 / async helpers -------------------
__device__ __forceinline__ uint32_t f2tf(float f) {
    uint32_t u;
    asm("cvt.rna.tf32.f32 %0, %1;" : "=r"(u) : "f"(f));
    return u;
}
__device__ __forceinline__ void mma8(float* c, const uint32_t* a, uint32_t b0, uint32_t b1) {
    asm volatile(
        "mma.sync.aligned.m16n8k8.row.col.f32.tf32.tf32.f32 "
        "{%0,%1,%2,%3}, {%4,%5,%6,%7}, {%8,%9}, {%0,%1,%2,%3};\n"
        : "+f"(c[0]), "+f"(c[1]), "+f"(c[2]), "+f"(c[3])
        : "r"(a[0]), "r"(a[1]), "r"(a[2]), "r"(a[3]), "r"(b0), "r"(b1));
}
__device__ __forceinline__ uint32_t smem_u32(const void* p) {
    uint32_t a;
    asm("{ .reg .u64 t; cvta.to.shared.u64 t, %1; cvt.u32.u64 %0, t; }" : "=r"(a) : "l"(p));
    return a;
}
__device__ __forceinline__ void cpasync16(uint32_t dst, const void* src) {
    asm volatile("cp.async.ca.shared.global [%0], [%1], 16;\n" :: "r"(dst), "l"(src));
}
#define CP_COMMIT() asm volatile("cp.async.commit_group;\n" ::: "memory")
#define CP_WAIT(N) asm volatile("cp.async.wait_group %0;\n" :: "n"(N) : "memory")

// ------------------- fast exp2 on the FMA pipe (poly, abs err ~2e-8) -------------
// valid for x <= 0 (softmax domain); clamp makes -1e30 masks -> 2^-126*1 ~ 0.
__device__ __forceinline__ float fexp2(float x) {
    x = fmaxf(x, -126.0f);
    int ei = __float2int_rd(x);
    float f = x - (float)ei;
    float p = 1.535336188319500e-4f;
    p = fmaf(p, f, 1.339887440266574e-3f);
    p = fmaf(p, f, 9.618437357674640e-3f);
    p = fmaf(p, f, 5.550332471162809e-2f);
    p = fmaf(p, f, 2.402264791363012e-1f);
    p = fmaf(p, f, 6.931472028550421e-1f);
    p = fmaf(p, f, 1.0f);
    return p * __int_as_float((ei + 127) << 23);
}

// ------------------- RoPE frequency table -------------------
__global__ void freq_kernel() {
    int i = threadIdx.x;
    g_invfreq[i] = pow(10000.0, -(double)i / 64.0);
}

// ------------------- weight tf32 pre-round (float4 streaming) -------------------
__global__ __launch_bounds__(256) void round4_kernel(const float* __restrict__ in,
                                                     float* __restrict__ out) {
    int i = (blockIdx.x * 256 + threadIdx.x) * 4;
    float4 v = *(const float4*)&in[i];
    float4 o;
    o.x = __uint_as_float(f2tf(v.x));
    o.y = __uint_as_float(f2tf(v.y));
    o.z = __uint_as_float(f2tf(v.z));
    o.w = __uint_as_float(f2tf(v.w));
    *(float4*)&out[i] = o;
}

// ------------------- EMA: 3-pass exact chunked scan (float4) -------------------
__global__ __launch_bounds__(256) void ema_local_kernel(const float* __restrict__ X) {
    int gidx = blockIdx.x * 256 + threadIdx.x;
    int c = gidx >> 9;
    int d4 = (gidx & 511) << 2;
    float4 m = make_float4(0.f, 0.f, 0.f, 0.f);
    int t0 = c * EMA_L;
#pragma unroll 2
    for (int i = 0; i < EMA_L; i++) {
        size_t off = (size_t)(t0 + i) * DD + d4;
        float4 x = *(const float4*)&X[off];
        m.x = fmaf(BETA, m.x, ALPHA * x.x);
        m.y = fmaf(BETA, m.y, ALPHA * x.y);
        m.z = fmaf(BETA, m.z, ALPHA * x.z);
        m.w = fmaf(BETA, m.w, ALPHA * x.w);
        *(float4*)&g_l2[off] = m;
        float4 xr;
        xr.x = __uint_as_float(f2tf(x.x));
        xr.y = __uint_as_float(f2tf(x.y));
        xr.z = __uint_as_float(f2tf(x.z));
        xr.w = __uint_as_float(f2tf(x.w));
        *(float4*)&g_xr[off] = xr;
    }
    *(float4*)&g_carry[c * DD + d4] = m;
}

__global__ void ema_scan_kernel() {
    int d4 = (blockIdx.x * 256 + threadIdx.x) * 4;
    float bl = 1.f;
#pragma unroll
    for (int i = 0; i < EMA_L; i++) bl *= BETA;
    float4 m = make_float4(0.f, 0.f, 0.f, 0.f);
#pragma unroll
    for (int c = 0; c < EMA_NC; c++) {
        *(float4*)&g_prefix[c * DD + d4] = m;
        float4 cr = *(const float4*)&g_carry[c * DD + d4];
        m.x = fmaf(bl, m.x, cr.x);
        m.y = fmaf(bl, m.y, cr.y);
        m.z = fmaf(bl, m.z, cr.z);
        m.w = fmaf(bl, m.w, cr.w);
    }
}

__global__ __launch_bounds__(256) void ema_fix_kernel() {
    int gidx = blockIdx.x * 256 + threadIdx.x;
    int c = (gidx >> 9) + 1;
    int d4 = (gidx & 511) << 2;
    float4 p = *(const float4*)&g_prefix[c * DD + d4];
    float f = BETA;
    int t0 = c * EMA_L;
#pragma unroll 2
    for (int i = 0; i < EMA_L; i++) {
        size_t off = (size_t)(t0 + i) * DD + d4;
        float4 v = *(float4*)&g_l2[off];
        v.x = fmaf(f, p.x, v.x);
        v.y = fmaf(f, p.y, v.y);
        v.z = fmaf(f, p.z, v.z);
        v.w = fmaf(f, p.w, v.w);
        *(float4*)&g_l2[off] = v;
        f *= BETA;
    }
}

// ------------------- TF32 GEMM v3: 3-stage cp.async pipeline -------------------
// block 128x128, BK=32, 256 threads, 8 warps (2m x 4n), warp tile 64x32.
// ALL inputs must be tf32-pre-rounded in gmem.
#define AP 36
#define BP 132
#define ASZ (128 * AP)
#define BSZ (32 * BP)
#define STGW (ASZ + BSZ)
#define MM_SMEM_BYTES (3 * STGW * 4)

__device__ __forceinline__ void mm_issue(uint32_t sbase, const float* Ax, const float* Bx,
                                         const uint32_t* aOffs, const uint32_t* bOffs,
                                         int N, int K) {
#pragma unroll
    for (int u = 0; u < 4; u++) cpasync16(sbase + aOffs[u], Ax + (size_t)(32 * u) * K);
#pragma unroll
    for (int u = 0; u < 4; u++) cpasync16(sbase + bOffs[u], Bx + (size_t)(8 * u) * N);
    CP_COMMIT();
}

// EPI: 0 = none, 1 = bias + silu, 2 = store tf32-rounded
template <int EPI>
__device__ __forceinline__ void mm_core(
    const float* __restrict__ A, const float* __restrict__ B,
    const float* __restrict__ bias, float* __restrict__ C,
    int N, int K, int bx, int by, uint32_t* sm)
{
    const int tid = threadIdx.x;
    const int aRow = tid >> 3;
    const int aCol = (tid & 7) * 4;
    const int bRow = tid >> 5;
    const int bCol = (tid & 31) * 4;

    const float* Asrc = A + (size_t)(by * 128 + aRow) * K + aCol;
    const float* Bsrc = B + (size_t)bRow * N + bx * 128 + bCol;

    const uint32_t sb = smem_u32(sm);
    uint32_t aOffs[4], bOffs[4];
#pragma unroll
    for (int u = 0; u < 4; u++) {
        aOffs[u] = (uint32_t)(((aRow + 32 * u) * AP + aCol) * 4);
        bOffs[u] = (uint32_t)((ASZ + (bRow + 8 * u) * BP + bCol) * 4);
    }

    const int lane = tid & 31;
    const int wid = tid >> 5;
    const int m0 = (wid >> 2) * 64;
    const int n0 = (wid & 3) * 32;
    const int g = lane >> 2;
    const int q = lane & 3;

    const int iters = K / 32;
    mm_issue(sb, Asrc, Bsrc, aOffs, bOffs, N, K);
    mm_issue(sb + STGW * 4, Asrc + 32, Bsrc + (size_t)32 * N, aOffs, bOffs, N, K);

    float acc[4][4][4];
#pragma unroll
    for (int i = 0; i < 4; i++)
#pragma unroll
        for (int j = 0; j < 4; j++)
#pragma unroll
            for (int c = 0; c < 4; c++) acc[i][j][c] = 0.f;

    for (int it = 0; it < iters; it++) {
        CP_WAIT(1);
        __syncthreads();

        const int nt = it + 2;
        if (nt < iters) {
            mm_issue(sb + (uint32_t)((nt % 3) * STGW * 4),
                     Asrc + (size_t)nt * 32, Bsrc + (size_t)nt * 32 * N,
                     aOffs, bOffs, N, K);
        } else {
            CP_COMMIT();
        }

        const uint32_t* As = sm + (it % 3) * STGW;
        const uint32_t* Bs = As + ASZ;

#pragma unroll
        for (int kk = 0; kk < 4; kk++) {
            const int ks = kk * 8;
            uint32_t af[4][4], bf[4][2];
#pragma unroll
            for (int i = 0; i < 4; i++) {
                const int mr = m0 + i * 16 + g;
                af[i][0] = As[mr * AP + ks + q];
                af[i][1] = As[(mr + 8) * AP + ks + q];
                af[i][2] = As[mr * AP + ks + q + 4];
                af[i][3] = As[(mr + 8) * AP + ks + q + 4];
            }
#pragma unroll
            for (int j = 0; j < 4; j++) {
                const int nc = n0 + j * 8 + g;
                bf[j][0] = Bs[(ks + q) * BP + nc];
                bf[j][1] = Bs[(ks + q + 4) * BP + nc];
            }
#pragma unroll
            for (int i = 0; i < 4; i++)
#pragma unroll
                for (int j = 0; j < 4; j++)
                    mma8(acc[i][j], af[i], bf[j][0], bf[j][1]);
        }
    }

#pragma unroll
    for (int i = 0; i < 4; i++) {
#pragma unroll
        for (int j = 0; j < 4; j++) {
            const int row0 = by * 128 + m0 + i * 16 + g;
            const int col = bx * 128 + n0 + j * 8 + 2 * q;
            float v0 = acc[i][j][0], v1 = acc[i][j][1];
            float v2 = acc[i][j][2], v3 = acc[i][j][3];
            if (EPI == 1) {
                float b0v = bias[col], b1v = bias[col + 1];
                v0 += b0v; v1 += b1v; v2 += b0v; v3 += b1v;
                v0 = v0 / (1.f + __expf(-v0));
                v1 = v1 / (1.f + __expf(-v1));
                v2 = v2 / (1.f + __expf(-v2));
                v3 = v3 / (1.f + __expf(-v3));
            }
            if (EPI == 2) {
                v0 = __uint_as_float(f2tf(v0));
                v1 = __uint_as_float(f2tf(v1));
                v2 = __uint_as_float(f2tf(v2));
                v3 = __uint_as_float(f2tf(v3));
            }
            *(float2*)&C[(size_t)row0 * N + col] = make_float2(v0, v1);
            *(float2*)&C[(size_t)(row0 + 8) * N + col] = make_float2(v2, v3);
        }
    }
}

template <int EPI>
__global__ __launch_bounds__(256, 2) void mm3(
    const float* __restrict__ A, const float* __restrict__ B,
    const float* __restrict__ bias, float* __restrict__ C, int N, int K)
{
    extern __shared__ uint32_t sm[];
    mm_core<EPI>(A, B, bias, C, N, K, blockIdx.x, blockIdx.y, sm);
}

__global__ __launch_bounds__(256, 2) void mm3_kv(
    const float* __restrict__ A,
    const float* __restrict__ B0, const float* __restrict__ B1,
    float* __restrict__ C0, float* __restrict__ C1, int K)
{
    extern __shared__ uint32_t sm[];
    const int sel = blockIdx.x >> 2;
    mm_core<2>(A, sel ? B1 : B0, nullptr, sel ? C1 : C0,
               DKV, K, blockIdx.x & 3, blockIdx.y, sm);
}

// ------------------- router (stores tf32-rounded fused) -------------------
__global__ __launch_bounds__(256) void router_fused_kernel(
    const float* __restrict__ X, const float* __restrict__ Wr2, const float* __restrict__ br2)
{
    const int t = blockIdx.x;
    const int tid = threadIdx.x;
    __shared__ float red[512];
    __shared__ float lam[2];

    float s0 = 0.f, s1 = 0.f;
    for (int j = tid; j < RDIM; j += 256) {
        float hv = g_h[t * RDIM + j];
        s0 = fmaf(hv, Wr2[2 * j + 0], s0);
        s1 = fmaf(hv, Wr2[2 * j + 1], s1);
    }
    red[tid] = s0;
    red[256 + tid] = s1;
    __syncthreads();
    for (int off = 128; off > 0; off >>= 1) {
        if (tid < off) {
            red[tid] += red[tid + off];
            red[256 + tid] += red[256 + tid + off];
        }
        __syncthreads();
    }
    if (tid == 0) {
        float a = red[0] + br2[0];
        float b = red[256] + br2[1];
        float mx = fmaxf(a, b);
        float e0 = __expf(a - mx), e1 = __expf(b - mx);
        float inv = 1.f / (e0 + e1);
        lam[0] = e0 * inv;
        lam[1] = e1 * inv;
    }
    __syncthreads();
    float l0 = lam[0], l1 = lam[1];
    for (int c = tid * 4; c < DD; c += 1024) {
        float4 x4 = *(const float4*)&X[t * DD + c];
        float4 m4 = *(const float4*)&g_l2[t * DD + c];
        float4 o;
        o.x = __uint_as_float(f2tf(fmaf(l0, x4.x, l1 * m4.x)));
        o.y = __uint_as_float(f2tf(fmaf(l0, x4.y, l1 * m4.y)));
        o.z = __uint_as_float(f2tf(fmaf(l0, x4.z, l1 * m4.z)));
        o.w = __uint_as_float(f2tf(fmaf(l0, x4.w, l1 * m4.w)));
        *(float4*)&g_fused[t * DD + c] = o;
    }
}

// ------------------- RoPE (table-driven; stores tf32-rounded, optional scale) ----
__global__ __launch_bounds__(256) void rope_kernel(float* __restrict__ M, int rowStride,
                                                   int nheads, float scale) {
    const int t = blockIdx.x;
    const int tid = threadIdx.x;
    const int hh = tid >> 6;
    const int i = tid & 63;
    const double inv = g_invfreq[i];
    const float ang = (float)((double)t * inv);
    float s, c;
    sincosf(ang, &s, &c);
    for (int head = hh; head < nheads; head += 4) {
        const int base = t * rowStride + head * HDIM;
        float x1 = M[base + i];
        float x2 = M[base + 64 + i];
        float o1 = (x1 * c - x2 * s) * scale;
        float o2 = fmaf(x2, c, x1 * s) * scale;
        M[base + i] = __uint_as_float(f2tf(o1));
        M[base + 64 + i] = __uint_as_float(f2tf(o2));
    }
}

// ------------------- flash attention (causal GQA, tf32 mma, cp.async, poly exp2) --
#define KPAD 132
#define TILE_W (64 * KPAD)
#define ATTN_SMEM_BYTES (4 * TILE_W * 4)

__global__ __launch_bounds__(256) void attn_kernel() {
    extern __shared__ uint32_t smw[];

    const int qt = (int)gridDim.x - 1 - (int)blockIdx.x;
    const int hp2 = blockIdx.y;
    const int tid = threadIdx.x;
    const int lane = tid & 31;
    const int wid = tid >> 5;
    const int hp = wid >> 2;
    const int ws = wid & 3;
    const int h = 2 * hp2 + hp;
    const int kvh = hp2 >> 1;
    const int g = lane >> 2;
    const int q = lane & 3;
    const int m0 = ws * 16;
    const int q0 = qt * 64;

    const uint32_t sb = smem_u32(smw);

#pragma unroll
    for (int u = 0; u < 8; u++) {
        int linear = u * 256 + tid;
        int r = linear >> 5;
        int c4 = (linear & 31) * 4;
        cpasync16(sb + (uint32_t)(2 * TILE_W + r * KPAD + c4) * 4,
                  &g_q[(size_t)(q0 + r) * DQ + (2 * hp2) * HDIM + c4]);
        cpasync16(sb + (uint32_t)(3 * TILE_W + r * KPAD + c4) * 4,
                  &g_q[(size_t)(q0 + r) * DQ + (2 * hp2 + 1) * HDIM + c4]);
    }
    CP_COMMIT();
    CP_WAIT(0);
    __syncthreads();

    uint32_t qf[16][4];
    {
        const uint32_t* Qb = smw + (hp ? 3 * TILE_W : 2 * TILE_W);
#pragma unroll
        for (int kk = 0; kk < 16; kk++) {
            const int base = (m0 + g) * KPAD + kk * 8 + q;
            qf[kk][0] = Qb[base];
            qf[kk][1] = Qb[base + 8 * KPAD];
            qf[kk][2] = Qb[base + 4];
            qf[kk][3] = Qb[base + 8 * KPAD + 4];
        }
    }
    __syncthreads();

    float oacc[16][4];
#pragma unroll
    for (int n = 0; n < 16; n++)
#pragma unroll
        for (int c = 0; c < 4; c++) oacc[n][c] = 0.f;
    float mrow[2] = {-1e30f, -1e30f};
    float lrow[2] = {0.f, 0.f};

    {
#pragma unroll
        for (int u = 0; u < 8; u++) {
            int linear = u * 256 + tid;
            int r = linear >> 5;
            int c4 = (linear & 31) * 4;
            cpasync16(sb + (uint32_t)(r * KPAD + c4) * 4,
                      &g_k[(size_t)r * DKV + kvh * HDIM + c4]);
            cpasync16(sb + (uint32_t)(TILE_W + r * KPAD + c4) * 4,
                      &g_v[(size_t)r * DKV + kvh * HDIM + c4]);
        }
        CP_COMMIT();
    }

    const int lA = 4 * g + (q >> 1);
    const int lB = lA + 2;
    const bool bq = (q & 1);

    for (int kt = 0; kt <= qt; kt++) {
        const int st = kt & 1;
        if (kt < qt) {
            const int k0n = (kt + 1) * 64;
            const uint32_t basew = (uint32_t)((st ^ 1) * 2 * TILE_W);
#pragma unroll
            for (int u = 0; u < 8; u++) {
                int linear = u * 256 + tid;
                int r = linear >> 5;
                int c4 = (linear & 31) * 4;
                cpasync16(sb + (basew + r * KPAD + c4) * 4,
                          &g_k[(size_t)(k0n + r) * DKV + kvh * HDIM + c4]);
                cpasync16(sb + (basew + TILE_W + r * KPAD + c4) * 4,
                          &g_v[(size_t)(k0n + r) * DKV + kvh * HDIM + c4]);
            }
            CP_COMMIT();
            CP_WAIT(1);
        } else {
            CP_WAIT(0);
        }
        __syncthreads();

        const uint32_t* Ksb = smw + st * 2 * TILE_W;
        const uint32_t* Vsb = Ksb + TILE_W;

        float sacc[8][4];
#pragma unroll
        for (int n = 0; n < 8; n++) {
#pragma unroll
            for (int c = 0; c < 4; c++) sacc[n][c] = 0.f;
            const uint32_t* bb = Ksb + (n * 8 + g) * KPAD + q;
#pragma unroll
            for (int kk = 0; kk < 16; kk++) {
                uint32_t b0 = bb[kk * 8];
                uint32_t b1 = bb[kk * 8 + 4];
                mma8(sacc[n], qf[kk], b0, b1);
            }
        }

        if (kt == qt) {
#pragma unroll
            for (int n = 0; n < 8; n++) {
                const int col0 = n * 8 + 2 * q;
                const int rA = m0 + g, rB = m0 + g + 8;
                if (col0 > rA) sacc[n][0] = -1e30f;
                if (col0 + 1 > rA) sacc[n][1] = -1e30f;
                if (col0 > rB) sacc[n][2] = -1e30f;
                if (col0 + 1 > rB) sacc[n][3] = -1e30f;
            }
        }

        float mx0 = -1e30f, mx1 = -1e30f;
#pragma unroll
        for (int n = 0; n < 8; n++) {
            mx0 = fmaxf(mx0, fmaxf(sacc[n][0], sacc[n][1]));
            mx1 = fmaxf(mx1, fmaxf(sacc[n][2], sacc[n][3]));
        }
        mx0 = fmaxf(mx0, __shfl_xor_sync(0xffffffffu, mx0, 1));
        mx0 = fmaxf(mx0, __shfl_xor_sync(0xffffffffu, mx0, 2));
        mx1 = fmaxf(mx1, __shfl_xor_sync(0xffffffffu, mx1, 1));
        mx1 = fmaxf(mx1, __shfl_xor_sync(0xffffffffu, mx1, 2));

        const float nm0 = fmaxf(mrow[0], mx0);
        const float nm1 = fmaxf(mrow[1], mx1);
        const float corr0 = fexp2(mrow[0] - nm0);
        const float corr1 = fexp2(mrow[1] - nm1);
        float rs0 = 0.f, rs1 = 0.f;
#pragma unroll
        for (int n = 0; n < 8; n++) {
            sacc[n][0] = fexp2(sacc[n][0] - nm0);
            sacc[n][1] = fexp2(sacc[n][1] - nm0);
            sacc[n][2] = fexp2(sacc[n][2] - nm1);
            sacc[n][3] = fexp2(sacc[n][3] - nm1);
            rs0 += sacc[n][0] + sacc[n][1];
            rs1 += sacc[n][2] + sacc[n][3];
        }
        rs0 += __shfl_xor_sync(0xffffffffu, rs0, 1);
        rs0 += __shfl_xor_sync(0xffffffffu, rs0, 2);
        rs1 += __shfl_xor_sync(0xffffffffu, rs1, 1);
        rs1 += __shfl_xor_sync(0xffffffffu, rs1, 2);
        lrow[0] = lrow[0] * corr0 + rs0;
        lrow[1] = lrow[1] * corr1 + rs1;
        mrow[0] = nm0;
        mrow[1] = nm1;
#pragma unroll
        for (int n = 0; n < 16; n++) {
            oacc[n][0] *= corr0;
            oacc[n][1] *= corr0;
            oacc[n][2] *= corr1;
            oacc[n][3] *= corr1;
        }

#pragma unroll
        for (int kk = 0; kk < 8; kk++) {
            float v0 = __shfl_sync(0xffffffffu, sacc[kk][0], lA);
            float v1 = __shfl_sync(0xffffffffu, sacc[kk][1], lA);
            float v2 = __shfl_sync(0xffffffffu, sacc[kk][2], lA);
            float v3 = __shfl_sync(0xffffffffu, sacc[kk][3], lA);
            float w0 = __shfl_sync(0xffffffffu, sacc[kk][0], lB);
            float w1 = __shfl_sync(0xffffffffu, sacc[kk][1], lB);
            float w2 = __shfl_sync(0xffffffffu, sacc[kk][2], lB);
            float w3 = __shfl_sync(0xffffffffu, sacc[kk][3], lB);
            uint32_t pa[4];
            pa[0] = f2tf(bq ? v1 : v0);
            pa[1] = f2tf(bq ? v3 : v2);
            pa[2] = f2tf(bq ? w1 : w0);
            pa[3] = f2tf(bq ? w3 : w2);
            const uint32_t* vb = Vsb + (kk * 8 + q) * KPAD + g;
#pragma unroll
            for (int n = 0; n < 16; n++) {
                uint32_t b0 = vb[n * 8];
                uint32_t b1 = vb[4 * KPAD + n * 8];
                mma8(oacc[n], pa, b0, b1);
            }
        }
        __syncthreads();
    }

    const float inv0 = 1.f / lrow[0];
    const float inv1 = 1.f / lrow[1];
    const int rowA = q0 + m0 + g;
    const int rowB = rowA + 8;
#pragma unroll
    for (int n = 0; n < 16; n++) {
        const int col = h * HDIM + n * 8 + 2 * q;
        *(float2*)&g_attn[(size_t)rowA * DQ + col] = make_float2(
            __uint_as_float(f2tf(oacc[n][0] * inv0)),
            __uint_as_float(f2tf(oacc[n][1] * inv0)));
        *(float2*)&g_attn[(size_t)rowB * DQ + col] = make_float2(
            __uint_as_float(f2tf(oacc[n][2] * inv1)),
            __uint_as_float(f2tf(oacc[n][3] * inv1)));
    }
}

// ------------------- host launch -------------------
extern "C" void kernel_launch(void* const* d_in, const int* in_sizes, int n_in,
                              void* d_out, int out_size) {
    const float* X   = (const float*)d_in[0];
    const float* Wq  = (const float*)d_in[1];
    const float* Wk  = (const float*)d_in[2];
    const float* Wv  = (const float*)d_in[3];
    const float* Wo  = (const float*)d_in[4];
    const float* Wr1 = (const float*)d_in[5];
    const float* br1 = (const float*)d_in[6];
    const float* Wr2 = (const float*)d_in[7];
    const float* br2 = (const float*)d_in[8];
    float* out = (float*)d_out;

    float *p_q, *p_h, *p_fused, *p_k, *p_v, *p_attn;
    float *p_xr, *p_wq, *p_wk, *p_wv, *p_wo, *p_wr1;
    cudaGetSymbolAddress((void**)&p_q, g_q);
    cudaGetSymbolAddress((void**)&p_h, g_h);
    cudaGetSymbolAddress((void**)&p_fused, g_fused);
    cudaGetSymbolAddress((void**)&p_k, g_k);
    cudaGetSymbolAddress((void**)&p_v, g_v);
    cudaGetSymbolAddress((void**)&p_attn, g_attn);
    cudaGetSymbolAddress((void**)&p_xr, g_xr);
    cudaGetSymbolAddress((void**)&p_wq, g_wq);
    cudaGetSymbolAddress((void**)&p_wk, g_wk);
    cudaGetSymbolAddress((void**)&p_wv, g_wv);
    cudaGetSymbolAddress((void**)&p_wo, g_wo);
    cudaGetSymbolAddress((void**)&p_wr1, g_wr1);

    cudaFuncSetAttribute(attn_kernel, cudaFuncAttributeMaxDynamicSharedMemorySize, ATTN_SMEM_BYTES);
    cudaFuncSetAttribute(mm3<0>, cudaFuncAttributeMaxDynamicSharedMemorySize, MM_SMEM_BYTES);
    cudaFuncSetAttribute(mm3<1>, cudaFuncAttributeMaxDynamicSharedMemorySize, MM_SMEM_BYTES);
    cudaFuncSetAttribute(mm3<2>, cudaFuncAttributeMaxDynamicSharedMemorySize, MM_SMEM_BYTES);
    cudaFuncSetAttribute(mm3_kv, cudaFuncAttributeMaxDynamicSharedMemorySize, MM_SMEM_BYTES);

    // RoPE freq table + weight pre-rounding (tf32)
    freq_kernel<<<1, 64>>>();
    round4_kernel<<<(DD * DQ) / 1024, 256>>>(Wq, p_wq);
    round4_kernel<<<(DD * DKV) / 1024, 256>>>(Wk, p_wk);
    round4_kernel<<<(DD * DKV) / 1024, 256>>>(Wv, p_wv);
    round4_kernel<<<(DQ * DD) / 1024, 256>>>(Wo, p_wo);
    round4_kernel<<<(DD * RDIM) / 1024, 256>>>(Wr1, p_wr1);

    // EMA (also emits X_r)
    ema_local_kernel<<<(EMA_NC * DD / 4) / 256, 256>>>(X);
    ema_scan_kernel<<<2, 256>>>();
    ema_fix_kernel<<<((EMA_NC - 1) * DD / 4) / 256, 256>>>();

    // q = X @ Wq
    mm3<2><<<dim3(DQ / 128, TT / 128), 256, MM_SMEM_BYTES>>>(p_xr, p_wq, nullptr, p_q, DQ, DD);
    // h = silu(q @ Wr1 + br1)
    mm3<1><<<dim3(RDIM / 128, TT / 128), 256, MM_SMEM_BYTES>>>(p_q, p_wr1, br1, p_h, RDIM, DQ);
    // lam + fused
    router_fused_kernel<<<TT, 256>>>(X, Wr2, br2);
    // k, v fused launch
    mm3_kv<<<dim3(2 * DKV / 128, TT / 128), 256, MM_SMEM_BYTES>>>(p_fused, p_wk, p_wv, p_k, p_v, DD);
    // RoPE: q gets softmax scale * log2e folded in; k plain
    rope_kernel<<<TT, 256>>>(p_q, DQ, NH, ATTN_SCALE * LOG2E);
    rope_kernel<<<TT, 256>>>(p_k, DKV, NKV, 1.0f);
    // attention
    attn_kernel<<<dim3(TT / 64, NH / 2), 256, ATTN_SMEM_BYTES>>>();
    // out = attn @ Wo
    mm3<0><<<dim3(DD / 128, TT / 128), 256, MM_SMEM_BYTES>>>(p_attn, p_wo, nullptr, out, DD, DQ);
}

// round 15
// speedup vs baseline: 1.0564x; 1.0564x over previous
#include <cuda_runtime.h>
#include <cuda_fp16.h>
#include <math.h>
#include <stdint.h>

#define TT 2048
#define DD 2048
#define NH 16
#define NKV 4
#define HDIM 128
#define DQ 2048    // NH*HD
#define DKV 512    // NKV*HD
#define RDIM 1024  // D/2
#define EMA_L 64
#define EMA_NC 32

#define BETA 0.9f
#define ALPHA 0.1f
#define ATTN_SCALE 0.08838834764831843f  // 1/sqrt(128)
#define LOG2E 1.4426950408889634f

// ------------------- scratch -------------------
__device__ float g_l2[TT * DD];
__device__ float g_carry[EMA_NC * DD];
__device__ float g_prefix[EMA_NC * DD];
__device__ double g_invfreq[64];
// fp16 activations
__device__ __half g_xr[TT * DD];
__device__ __half g_q[TT * DQ];
__device__ __half g_h[TT * RDIM];
__device__ __half g_fused[TT * DD];
__device__ __half g_k[TT * DKV];
__device__ __half g_v[TT * DKV];
__device__ __half g_vi[TT * DKV];   // k-pair interleaved: half2[T/2][DKV]
__device__ __half g_attn[TT * DQ];
// fp16 weights, k-pair interleaved: half2[K/2][N]
__device__ __half g_wq[DD * DQ];
__device__ __half g_wk[DD * DKV];
__device__ __half g_wv[DD * DKV];
__device__ __half g_wo[DQ * DD];
__device__ __half g_wr1[DD * RDIM];

// ------------------- helpers -------------------
__device__ __forceinline__ uint32_t pack2(float a, float b) {
    __half2 h = __floats2half2_rn(a, b);
    return *(uint32_t*)&h;
}
__device__ __forceinline__ void mma16(float* c, const uint32_t* a, uint32_t b0, uint32_t b1) {
    asm volatile(
        "mma.sync.aligned.m16n8k16.row.col.f32.f16.f16.f32 "
        "{%0,%1,%2,%3}, {%4,%5,%6,%7}, {%8,%9}, {%0,%1,%2,%3};\n"
        : "+f"(c[0]), "+f"(c[1]), "+f"(c[2]), "+f"(c[3])
        : "r"(a[0]), "r"(a[1]), "r"(a[2]), "r"(a[3]), "r"(b0), "r"(b1));
}
__device__ __forceinline__ uint32_t smem_u32(const void* p) {
    uint32_t a;
    asm("{ .reg .u64 t; cvta.to.shared.u64 t, %1; cvt.u32.u64 %0, t; }" : "=r"(a) : "l"(p));
    return a;
}
__device__ __forceinline__ void cpasync16(uint32_t dst, const void* src) {
    asm volatile("cp.async.ca.shared.global [%0], [%1], 16;\n" :: "r"(dst), "l"(src));
}
#define CP_COMMIT() asm volatile("cp.async.commit_group;\n" ::: "memory")
#define CP_WAIT(N) asm volatile("cp.async.wait_group %0;\n" :: "n"(N) : "memory")

// fast exp2 (poly on FMA pipe); valid for x <= 0
__device__ __forceinline__ float fexp2(float x) {
    x = fmaxf(x, -126.0f);
    int ei = __float2int_rd(x);
    float f = x - (float)ei;
    float p = 1.535336188319500e-4f;
    p = fmaf(p, f, 1.339887440266574e-3f);
    p = fmaf(p, f, 9.618437357674640e-3f);
    p = fmaf(p, f, 5.550332471162809e-2f);
    p = fmaf(p, f, 2.402264791363012e-1f);
    p = fmaf(p, f, 6.931472028550421e-1f);
    p = fmaf(p, f, 1.0f);
    return p * __int_as_float((ei + 127) << 23);
}

// ------------------- RoPE frequency table -------------------
__global__ void freq_kernel() {
    int i = threadIdx.x;
    g_invfreq[i] = pow(10000.0, -(double)i / 64.0);
}

// ------------------- weight convert: fp32 [K,N] -> fp16 k-pair-interleaved half2[K/2][N]
__global__ __launch_bounds__(256) void wconv_kernel(const float* __restrict__ in,
                                                    __half* __restrict__ outh, int N) {
    __half2* out = (__half2*)outh;
    int idx = blockIdx.x * 256 + threadIdx.x;
    int perRow = N >> 2;
    int k2 = idx / perRow;
    int c = (idx - k2 * perRow) << 2;
    float4 a = *(const float4*)&in[(size_t)(2 * k2) * N + c];
    float4 b = *(const float4*)&in[(size_t)(2 * k2 + 1) * N + c];
    __half2 o0 = __floats2half2_rn(a.x, b.x);
    __half2 o1 = __floats2half2_rn(a.y, b.y);
    __half2 o2 = __floats2half2_rn(a.z, b.z);
    __half2 o3 = __floats2half2_rn(a.w, b.w);
    uint4 st;
    st.x = *(uint32_t*)&o0; st.y = *(uint32_t*)&o1;
    st.z = *(uint32_t*)&o2; st.w = *(uint32_t*)&o3;
    *(uint4*)&out[(size_t)k2 * N + c] = st;
}

// ------------------- V interleave: g_v [T,DKV] -> g_vi half2[T/2][DKV] ------------
__global__ __launch_bounds__(256) void vinterleave_kernel() {
    __half2* out = (__half2*)g_vi;
    int idx = blockIdx.x * 256 + threadIdx.x;
    int perRow = DKV >> 2;
    int r2 = idx / perRow;
    int c = (idx - r2 * perRow) << 2;
    uint2 ua = *(const uint2*)&g_v[(size_t)(2 * r2) * DKV + c];
    uint2 ub = *(const uint2*)&g_v[(size_t)(2 * r2 + 1) * DKV + c];
    __half2 A01 = *(__half2*)&ua.x, A23 = *(__half2*)&ua.y;
    __half2 B01 = *(__half2*)&ub.x, B23 = *(__half2*)&ub.y;
    __half2 o0 = __lows2half2(A01, B01);
    __half2 o1 = __highs2half2(A01, B01);
    __half2 o2 = __lows2half2(A23, B23);
    __half2 o3 = __highs2half2(A23, B23);
    uint4 st;
    st.x = *(uint32_t*)&o0; st.y = *(uint32_t*)&o1;
    st.z = *(uint32_t*)&o2; st.w = *(uint32_t*)&o3;
    *(uint4*)&out[(size_t)r2 * DKV + c] = st;
}

// ------------------- EMA: 3-pass exact chunked scan; emits fp16 X_r --------------
__global__ __launch_bounds__(256) void ema_local_kernel(const float* __restrict__ X) {
    int gidx = blockIdx.x * 256 + threadIdx.x;
    int c = gidx >> 9;
    int d4 = (gidx & 511) << 2;
    float4 m = make_float4(0.f, 0.f, 0.f, 0.f);
    int t0 = c * EMA_L;
#pragma unroll 2
    for (int i = 0; i < EMA_L; i++) {
        size_t off = (size_t)(t0 + i) * DD + d4;
        float4 x = *(const float4*)&X[off];
        m.x = fmaf(BETA, m.x, ALPHA * x.x);
        m.y = fmaf(BETA, m.y, ALPHA * x.y);
        m.z = fmaf(BETA, m.z, ALPHA * x.z);
        m.w = fmaf(BETA, m.w, ALPHA * x.w);
        *(float4*)&g_l2[off] = m;
        __half2 h01 = __floats2half2_rn(x.x, x.y);
        __half2 h23 = __floats2half2_rn(x.z, x.w);
        uint2 st;
        st.x = *(uint32_t*)&h01; st.y = *(uint32_t*)&h23;
        *(uint2*)&g_xr[off] = st;
    }
    *(float4*)&g_carry[c * DD + d4] = m;
}

__global__ void ema_scan_kernel() {
    int d4 = (blockIdx.x * 256 + threadIdx.x) * 4;
    float bl = 1.f;
#pragma unroll
    for (int i = 0; i < EMA_L; i++) bl *= BETA;
    float4 m = make_float4(0.f, 0.f, 0.f, 0.f);
#pragma unroll
    for (int c = 0; c < EMA_NC; c++) {
        *(float4*)&g_prefix[c * DD + d4] = m;
        float4 cr = *(const float4*)&g_carry[c * DD + d4];
        m.x = fmaf(bl, m.x, cr.x);
        m.y = fmaf(bl, m.y, cr.y);
        m.z = fmaf(bl, m.z, cr.z);
        m.w = fmaf(bl, m.w, cr.w);
    }
}

__global__ __launch_bounds__(256) void ema_fix_kernel() {
    int gidx = blockIdx.x * 256 + threadIdx.x;
    int c = (gidx >> 9) + 1;
    int d4 = (gidx & 511) << 2;
    float4 p = *(const float4*)&g_prefix[c * DD + d4];
    float f = BETA;
    int t0 = c * EMA_L;
#pragma unroll 2
    for (int i = 0; i < EMA_L; i++) {
        size_t off = (size_t)(t0 + i) * DD + d4;
        float4 v = *(float4*)&g_l2[off];
        v.x = fmaf(f, p.x, v.x);
        v.y = fmaf(f, p.y, v.y);
        v.z = fmaf(f, p.z, v.z);
        v.w = fmaf(f, p.w, v.w);
        *(float4*)&g_l2[off] = v;
        f *= BETA;
    }
}

// ------------------- fp16 GEMM: 3-stage cp.async, m16n8k16 -------------------
// block 128x128, BK=32, 256 threads, 8 warps (2m x 4n), warp tile 64x32.
// A: fp16 [M,K] row-major. B: fp16 half2[K/2][N] k-pair interleaved.
#define AP2 20                      // A smem pitch (half2 units per row)
#define BP2 132                     // B smem pitch (half2 units per k2 row)
#define ASZB (128 * AP2 * 4)        // 10240 B
#define BSZB (16 * BP2 * 4)         // 8448 B
#define STGB (ASZB + BSZB)          // 18688 B
#define STGW (STGB / 4)
#define MM_SMEM_BYTES (3 * STGB)    // 56064 B

__device__ __forceinline__ void mm_issue(uint32_t sbase, const __half* Ax,
                                         const __half2* Bx,
                                         const uint32_t* aOffs, const uint32_t* bOffs,
                                         int N, int K) {
#pragma unroll
    for (int u = 0; u < 2; u++) cpasync16(sbase + aOffs[u], Ax + (size_t)(64 * u) * K);
#pragma unroll
    for (int u = 0; u < 2; u++) cpasync16(sbase + bOffs[u], Bx + (size_t)(8 * u) * N);
    CP_COMMIT();
}

// EPI: 0 = fp32 store, 1 = bias+silu fp16 store, 2 = fp16 store
template <int EPI>
__device__ __forceinline__ void mm_core(
    const __half* __restrict__ A, const __half* __restrict__ Bh,
    const float* __restrict__ bias, void* __restrict__ C,
    int N, int K, int bx, int by, uint32_t* sm)
{
    const __half2* B2 = (const __half2*)Bh;
    const int tid = threadIdx.x;
    const int aRow = tid >> 2;          // 0..63
    const int aSeg = tid & 3;           // 16B segs of 64B row
    const int bRow = tid >> 5;          // 0..7
    const int bSeg = tid & 31;          // 16B segs of 512B row

    const __half* Asrc = A + (size_t)(by * 128 + aRow) * K + aSeg * 8;
    const __half2* Bsrc = B2 + (size_t)bRow * N + bx * 128 + bSeg * 4;

    const uint32_t sb = smem_u32(sm);
    uint32_t aOffs[2], bOffs[2];
#pragma unroll
    for (int u = 0; u < 2; u++) {
        aOffs[u] = (uint32_t)((aRow + 64 * u) * (AP2 * 4) + aSeg * 16);
        bOffs[u] = (uint32_t)(ASZB + (bRow + 8 * u) * (BP2 * 4) + bSeg * 16);
    }

    const int lane = tid & 31;
    const int wid = tid >> 5;
    const int m0 = (wid >> 2) * 64;
    const int n0 = (wid & 3) * 32;
    const int g = lane >> 2;
    const int q = lane & 3;

    const int iters = K / 32;
    mm_issue(sb, Asrc, Bsrc, aOffs, bOffs, N, K);
    mm_issue(sb + STGB, Asrc + 32, Bsrc + (size_t)16 * N, aOffs, bOffs, N, K);

    float acc[4][4][4];
#pragma unroll
    for (int i = 0; i < 4; i++)
#pragma unroll
        for (int j = 0; j < 4; j++)
#pragma unroll
            for (int c = 0; c < 4; c++) acc[i][j][c] = 0.f;

    for (int it = 0; it < iters; it++) {
        CP_WAIT(1);
        __syncthreads();

        const int nt = it + 2;
        if (nt < iters) {
            mm_issue(sb + (uint32_t)((nt % 3) * STGB),
                     Asrc + (size_t)nt * 32, Bsrc + (size_t)nt * 16 * N,
                     aOffs, bOffs, N, K);
        } else {
            CP_COMMIT();
        }

        const uint32_t* As = sm + (it % 3) * STGW;          // half2 words, pitch AP2
        const uint32_t* Bs = As + ASZB / 4;                  // pitch BP2

#pragma unroll
        for (int kk = 0; kk < 2; kk++) {
            const int ks = kk * 8;
            uint32_t af[4][4], bf[4][2];
#pragma unroll
            for (int i = 0; i < 4; i++) {
                const int mr = m0 + i * 16 + g;
                af[i][0] = As[mr * AP2 + ks + q];
                af[i][1] = As[(mr + 8) * AP2 + ks + q];
                af[i][2] = As[mr * AP2 + ks + q + 4];
                af[i][3] = As[(mr + 8) * AP2 + ks + q + 4];
            }
#pragma unroll
            for (int j = 0; j < 4; j++) {
                const int nc = n0 + j * 8 + g;
                bf[j][0] = Bs[(ks + q) * BP2 + nc];
                bf[j][1] = Bs[(ks + q + 4) * BP2 + nc];
            }
#pragma unroll
            for (int i = 0; i < 4; i++)
#pragma unroll
                for (int j = 0; j < 4; j++)
                    mma16(acc[i][j], af[i], bf[j][0], bf[j][1]);
        }
    }

#pragma unroll
    for (int i = 0; i < 4; i++) {
#pragma unroll
        for (int j = 0; j < 4; j++) {
            const int row0 = by * 128 + m0 + i * 16 + g;
            const int col = bx * 128 + n0 + j * 8 + 2 * q;
            float v0 = acc[i][j][0], v1 = acc[i][j][1];
            float v2 = acc[i][j][2], v3 = acc[i][j][3];
            if (EPI == 1) {
                float b0v = bias[col], b1v = bias[col + 1];
                v0 += b0v; v1 += b1v; v2 += b0v; v3 += b1v;
                v0 = v0 / (1.f + __expf(-v0));
                v1 = v1 / (1.f + __expf(-v1));
                v2 = v2 / (1.f + __expf(-v2));
                v3 = v3 / (1.f + __expf(-v3));
            }
            if (EPI == 0) {
                float* Cf = (float*)C;
                *(float2*)&Cf[(size_t)row0 * N + col] = make_float2(v0, v1);
                *(float2*)&Cf[(size_t)(row0 + 8) * N + col] = make_float2(v2, v3);
            } else {
                __half* Ch = (__half*)C;
                __half2 h0 = __floats2half2_rn(v0, v1);
                __half2 h1 = __floats2half2_rn(v2, v3);
                *(__half2*)&Ch[(size_t)row0 * N + col] = h0;
                *(__half2*)&Ch[(size_t)(row0 + 8) * N + col] = h1;
            }
        }
    }
}

template <int EPI>
__global__ __launch_bounds__(256, 2) void mmh(
    const __half* __restrict__ A, const __half* __restrict__ B,
    const float* __restrict__ bias, void* __restrict__ C, int N, int K)
{
    extern __shared__ uint32_t sm[];
    mm_core<EPI>(A, B, bias, C, N, K, blockIdx.x, blockIdx.y, sm);
}

__global__ __launch_bounds__(256, 2) void mmh_kv(
    const __half* __restrict__ A,
    const __half* __restrict__ B0, const __half* __restrict__ B1,
    __half* __restrict__ C0, __half* __restrict__ C1, int K)
{
    extern __shared__ uint32_t sm[];
    const int sel = blockIdx.x >> 2;
    mm_core<2>(A, sel ? B1 : B0, nullptr, sel ? (void*)C1 : (void*)C0,
               DKV, K, blockIdx.x & 3, blockIdx.y, sm);
}

// ------------------- router (reads fp16 h; stores fp16 fused) -------------------
__global__ __launch_bounds__(256) void router_fused_kernel(
    const float* __restrict__ X, const float* __restrict__ Wr2, const float* __restrict__ br2)
{
    const int t = blockIdx.x;
    const int tid = threadIdx.x;
    __shared__ float red[512];
    __shared__ float lam[2];

    float s0 = 0.f, s1 = 0.f;
    for (int j = tid; j < RDIM; j += 256) {
        float hv = __half2float(g_h[t * RDIM + j]);
        s0 = fmaf(hv, Wr2[2 * j + 0], s0);
        s1 = fmaf(hv, Wr2[2 * j + 1], s1);
    }
    red[tid] = s0;
    red[256 + tid] = s1;
    __syncthreads();
    for (int off = 128; off > 0; off >>= 1) {
        if (tid < off) {
            red[tid] += red[tid + off];
            red[256 + tid] += red[256 + tid + off];
        }
        __syncthreads();
    }
    if (tid == 0) {
        float a = red[0] + br2[0];
        float b = red[256] + br2[1];
        float mx = fmaxf(a, b);
        float e0 = __expf(a - mx), e1 = __expf(b - mx);
        float inv = 1.f / (e0 + e1);
        lam[0] = e0 * inv;
        lam[1] = e1 * inv;
    }
    __syncthreads();
    float l0 = lam[0], l1 = lam[1];
    for (int c = tid * 4; c < DD; c += 1024) {
        float4 x4 = *(const float4*)&X[t * DD + c];
        float4 m4 = *(const float4*)&g_l2[t * DD + c];
        __half2 h01 = __floats2half2_rn(fmaf(l0, x4.x, l1 * m4.x),
                                        fmaf(l0, x4.y, l1 * m4.y));
        __half2 h23 = __floats2half2_rn(fmaf(l0, x4.z, l1 * m4.z),
                                        fmaf(l0, x4.w, l1 * m4.w));
        uint2 st;
        st.x = *(uint32_t*)&h01; st.y = *(uint32_t*)&h23;
        *(uint2*)&g_fused[t * DD + c] = st;
    }
}

// ------------------- RoPE (fp16 in place; optional scale) -------------------
__global__ __launch_bounds__(256) void rope_kernel(__half* __restrict__ M, int rowStride,
                                                   int nheads, float scale) {
    const int t = blockIdx.x;
    const int tid = threadIdx.x;
    const int hh = tid >> 6;
    const int i = tid & 63;
    const double inv = g_invfreq[i];
    const float ang = (float)((double)t * inv);
    float s, c;
    sincosf(ang, &s, &c);
    for (int head = hh; head < nheads; head += 4) {
        const int base = t * rowStride + head * HDIM;
        float x1 = __half2float(M[base + i]);
        float x2 = __half2float(M[base + 64 + i]);
        float o1 = (x1 * c - x2 * s) * scale;
        float o2 = fmaf(x2, c, x1 * s) * scale;
        M[base + i] = __float2half_rn(o1);
        M[base + 64 + i] = __float2half_rn(o2);
    }
}

// ------------------- flash attention (causal GQA, fp16 m16n8k16) -------------------
// grid (32, 8): 64 q-rows x 2 heads (same KV group). 256 threads (8 warps).
// smem: 4 slots of 17408B: [K0][V0][K1][V1]; Q staged via slots 0,1.
#define KP2 68                       // K/Q smem pitch (half2 per row)
#define VP2 132                      // V smem pitch (half2 per r2 row)
#define SLOT_B (64 * KP2 * 4)        // 17408
#define ATTN_SMEM_BYTES (4 * SLOT_B) // 69632

__global__ __launch_bounds__(256) void attn_kernel() {
    extern __shared__ uint32_t smw[];

    const int qt = (int)gridDim.x - 1 - (int)blockIdx.x;   // heavy first
    const int hp2 = blockIdx.y;
    const int tid = threadIdx.x;
    const int lane = tid & 31;
    const int wid = tid >> 5;
    const int hp = wid >> 2;
    const int ws = wid & 3;
    const int h = 2 * hp2 + hp;
    const int kvh = hp2 >> 1;
    const int g = lane >> 2;
    const int q = lane & 3;
    const int m0 = ws * 16;
    const int q0 = qt * 64;

    const uint32_t sb = smem_u32(smw);
    const __half2* Vg = (const __half2*)g_vi;

    // ---- stage Q of both heads into slots 0,1 ----
#pragma unroll
    for (int u = 0; u < 4; u++) {
        int linear = u * 256 + tid;           // 0..1023
        int r = linear >> 4;
        int s = linear & 15;
        cpasync16(sb + (uint32_t)(r * (KP2 * 4) + s * 16),
                  &g_q[(size_t)(q0 + r) * DQ + (2 * hp2) * HDIM + s * 8]);
        cpasync16(sb + (uint32_t)(SLOT_B + r * (KP2 * 4) + s * 16),
                  &g_q[(size_t)(q0 + r) * DQ + (2 * hp2 + 1) * HDIM + s * 8]);
    }
    CP_COMMIT();
    CP_WAIT(0);
    __syncthreads();

    uint32_t qf[8][4];
    {
        const uint32_t* Qb = smw + (hp ? SLOT_B / 4 : 0);
#pragma unroll
        for (int kk = 0; kk < 8; kk++) {
            const int base = (m0 + g) * KP2 + kk * 8 + q;
            qf[kk][0] = Qb[base];
            qf[kk][1] = Qb[base + 8 * KP2];
            qf[kk][2] = Qb[base + 4];
            qf[kk][3] = Qb[base + 8 * KP2 + 4];
        }
    }
    __syncthreads();

    float oacc[16][4];
#pragma unroll
    for (int n = 0; n < 16; n++)
#pragma unroll
        for (int c = 0; c < 4; c++) oacc[n][c] = 0.f;
    float mrow[2] = {-1e30f, -1e30f};
    float lrow[2] = {0.f, 0.f};

    // prefetch tile 0 into slots 0 (K), 1 (V)
    {
#pragma unroll
        for (int u = 0; u < 4; u++) {
            int linear = u * 256 + tid;
            int rk = linear >> 4, sk = linear & 15;
            cpasync16(sb + (uint32_t)(rk * (KP2 * 4) + sk * 16),
                      &g_k[(size_t)rk * DKV + kvh * HDIM + sk * 8]);
            int rv = linear >> 5, sv = linear & 31;
            cpasync16(sb + (uint32_t)(SLOT_B + rv * (VP2 * 4) + sv * 16),
                      Vg + (size_t)rv * DKV + kvh * HDIM + sv * 4);
        }
        CP_COMMIT();
    }

    for (int kt = 0; kt <= qt; kt++) {
        const int st = kt & 1;
        if (kt < qt) {
            const int k0n = (kt + 1) * 64;
            const uint32_t basew = (uint32_t)((st ^ 1) * 2 * SLOT_B);
#pragma unroll
            for (int u = 0; u < 4; u++) {
                int linear = u * 256 + tid;
                int rk = linear >> 4, sk = linear & 15;
                cpasync16(sb + basew + (uint32_t)(rk * (KP2 * 4) + sk * 16),
                          &g_k[(size_t)(k0n + rk) * DKV + kvh * HDIM + sk * 8]);
                int rv = linear >> 5, sv = linear & 31;
                cpasync16(sb + basew + SLOT_B + (uint32_t)(rv * (VP2 * 4) + sv * 16),
                          Vg + (size_t)(k0n / 2 + rv) * DKV + kvh * HDIM + sv * 4);
            }
            CP_COMMIT();
            CP_WAIT(1);
        } else {
            CP_WAIT(0);
        }
        __syncthreads();

        const uint32_t* Ks = smw + st * 2 * (SLOT_B / 4);
        const uint32_t* Vs = Ks + SLOT_B / 4;

        // ---- S = Q @ K^T : 16 x 64 per warp ----
        float sacc[8][4];
#pragma unroll
        for (int n = 0; n < 8; n++) {
#pragma unroll
            for (int c = 0; c < 4; c++) sacc[n][c] = 0.f;
            const uint32_t* bb = Ks + (n * 8 + g) * KP2 + q;
#pragma unroll
            for (int kk = 0; kk < 8; kk++) {
                uint32_t b0 = bb[kk * 8];
                uint32_t b1 = bb[kk * 8 + 4];
                mma16(sacc[n], qf[kk], b0, b1);
            }
        }

        // ---- causal mask (diagonal tile) ----
        if (kt == qt) {
#pragma unroll
            for (int n = 0; n < 8; n++) {
                const int col0 = n * 8 + 2 * q;
                const int rA = m0 + g, rB = m0 + g + 8;
                if (col0 > rA) sacc[n][0] = -1e30f;
                if (col0 + 1 > rA) sacc[n][1] = -1e30f;
                if (col0 > rB) sacc[n][2] = -1e30f;
                if (col0 + 1 > rB) sacc[n][3] = -1e30f;
            }
        }

        // ---- online softmax (base-2) ----
        float mx0 = -1e30f, mx1 = -1e30f;
#pragma unroll
        for (int n = 0; n < 8; n++) {
            mx0 = fmaxf(mx0, fmaxf(sacc[n][0], sacc[n][1]));
            mx1 = fmaxf(mx1, fmaxf(sacc[n][2], sacc[n][3]));
        }
        mx0 = fmaxf(mx0, __shfl_xor_sync(0xffffffffu, mx0, 1));
        mx0 = fmaxf(mx0, __shfl_xor_sync(0xffffffffu, mx0, 2));
        mx1 = fmaxf(mx1, __shfl_xor_sync(0xffffffffu, mx1, 1));
        mx1 = fmaxf(mx1, __shfl_xor_sync(0xffffffffu, mx1, 2));

        const float nm0 = fmaxf(mrow[0], mx0);
        const float nm1 = fmaxf(mrow[1], mx1);
        const float corr0 = fexp2(mrow[0] - nm0);
        const float corr1 = fexp2(mrow[1] - nm1);
        float rs0 = 0.f, rs1 = 0.f;
#pragma unroll
        for (int n = 0; n < 8; n++) {
            sacc[n][0] = fexp2(sacc[n][0] - nm0);
            sacc[n][1] = fexp2(sacc[n][1] - nm0);
            sacc[n][2] = fexp2(sacc[n][2] - nm1);
            sacc[n][3] = fexp2(sacc[n][3] - nm1);
            rs0 += sacc[n][0] + sacc[n][1];
            rs1 += sacc[n][2] + sacc[n][3];
        }
        rs0 += __shfl_xor_sync(0xffffffffu, rs0, 1);
        rs0 += __shfl_xor_sync(0xffffffffu, rs0, 2);
        rs1 += __shfl_xor_sync(0xffffffffu, rs1, 1);
        rs1 += __shfl_xor_sync(0xffffffffu, rs1, 2);
        lrow[0] = lrow[0] * corr0 + rs0;
        lrow[1] = lrow[1] * corr1 + rs1;
        mrow[0] = nm0;
        mrow[1] = nm1;
#pragma unroll
        for (int n = 0; n < 16; n++) {
            oacc[n][0] *= corr0;
            oacc[n][1] *= corr0;
            oacc[n][2] *= corr1;
            oacc[n][3] *= corr1;
        }

        // ---- O += P @ V : C-frag of S IS the A-frag of P (fp16 pairing) ----
#pragma unroll
        for (int kk = 0; kk < 4; kk++) {
            uint32_t pa[4];
            pa[0] = pack2(sacc[2 * kk][0], sacc[2 * kk][1]);
            pa[1] = pack2(sacc[2 * kk][2], sacc[2 * kk][3]);
            pa[2] = pack2(sacc[2 * kk + 1][0], sacc[2 * kk + 1][1]);
            pa[3] = pack2(sacc[2 * kk + 1][2], sacc[2 * kk + 1][3]);
            const uint32_t* vb0 = Vs + (8 * kk + q) * VP2 + g;
            const uint32_t* vb1 = Vs + (8 * kk + q + 4) * VP2 + g;
#pragma unroll
            for (int n = 0; n < 16; n++)
                mma16(oacc[n], pa, vb0[n * 8], vb1[n * 8]);
        }
        __syncthreads();
    }

    // ---- write O (fp16: A operand of the Wo GEMM) ----
    const float inv0 = 1.f / lrow[0];
    const float inv1 = 1.f / lrow[1];
    const int rowA = q0 + m0 + g;
    const int rowB = rowA + 8;
#pragma unroll
    for (int n = 0; n < 16; n++) {
        const int col = h * HDIM + n * 8 + 2 * q;
        __half2 h0 = __floats2half2_rn(oacc[n][0] * inv0, oacc[n][1] * inv0);
        __half2 h1 = __floats2half2_rn(oacc[n][2] * inv1, oacc[n][3] * inv1);
        *(__half2*)&g_attn[(size_t)rowA * DQ + col] = h0;
        *(__half2*)&g_attn[(size_t)rowB * DQ + col] = h1;
    }
}

// ------------------- host launch -------------------
extern "C" void kernel_launch(void* const* d_in, const int* in_sizes, int n_in,
                              void* d_out, int out_size) {
    const float* X   = (const float*)d_in[0];
    const float* Wq  = (const float*)d_in[1];
    const float* Wk  = (const float*)d_in[2];
    const float* Wv  = (const float*)d_in[3];
    const float* Wo  = (const float*)d_in[4];
    const float* Wr1 = (const float*)d_in[5];
    const float* br1 = (const float*)d_in[6];
    const float* Wr2 = (const float*)d_in[7];
    const float* br2 = (const float*)d_in[8];
    float* out = (float*)d_out;

    __half *p_q, *p_h, *p_fused, *p_k, *p_v, *p_attn, *p_xr;
    __half *p_wq, *p_wk, *p_wv, *p_wo, *p_wr1;
    cudaGetSymbolAddress((void**)&p_q, g_q);
    cudaGetSymbolAddress((void**)&p_h, g_h);
    cudaGetSymbolAddress((void**)&p_fused, g_fused);
    cudaGetSymbolAddress((void**)&p_k, g_k);
    cudaGetSymbolAddress((void**)&p_v, g_v);
    cudaGetSymbolAddress((void**)&p_attn, g_attn);
    cudaGetSymbolAddress((void**)&p_xr, g_xr);
    cudaGetSymbolAddress((void**)&p_wq, g_wq);
    cudaGetSymbolAddress((void**)&p_wk, g_wk);
    cudaGetSymbolAddress((void**)&p_wv, g_wv);
    cudaGetSymbolAddress((void**)&p_wo, g_wo);
    cudaGetSymbolAddress((void**)&p_wr1, g_wr1);

    cudaFuncSetAttribute(attn_kernel, cudaFuncAttributeMaxDynamicSharedMemorySize, ATTN_SMEM_BYTES);
    cudaFuncSetAttribute(mmh<0>, cudaFuncAttributeMaxDynamicSharedMemorySize, MM_SMEM_BYTES);
    cudaFuncSetAttribute(mmh<1>, cudaFuncAttributeMaxDynamicSharedMemorySize, MM_SMEM_BYTES);
    cudaFuncSetAttribute(mmh<2>, cudaFuncAttributeMaxDynamicSharedMemorySize, MM_SMEM_BYTES);
    cudaFuncSetAttribute(mmh_kv, cudaFuncAttributeMaxDynamicSharedMemorySize, MM_SMEM_BYTES);

    // freq table + weight convert (fp16, k-pair interleaved)
    freq_kernel<<<1, 64>>>();
    wconv_kernel<<<(DD / 2) * (DQ / 4) / 256, 256>>>(Wq, p_wq, DQ);
    wconv_kernel<<<(DD / 2) * (DKV / 4) / 256, 256>>>(Wk, p_wk, DKV);
    wconv_kernel<<<(DD / 2) * (DKV / 4) / 256, 256>>>(Wv, p_wv, DKV);
    wconv_kernel<<<(DQ / 2) * (DD / 4) / 256, 256>>>(Wo, p_wo, DD);
    wconv_kernel<<<(DD / 2) * (RDIM / 4) / 256, 256>>>(Wr1, p_wr1, RDIM);

    // EMA (also emits fp16 X_r)
    ema_local_kernel<<<(EMA_NC * DD / 4) / 256, 256>>>(X);
    ema_scan_kernel<<<2, 256>>>();
    ema_fix_kernel<<<((EMA_NC - 1) * DD / 4) / 256, 256>>>();

    // q = X @ Wq (fp16 out, pre-RoPE; feeds Wr1)
    mmh<2><<<dim3(DQ / 128, TT / 128), 256, MM_SMEM_BYTES>>>(p_xr, p_wq, nullptr, p_q, DQ, DD);
    // h = silu(q @ Wr1 + br1)
    mmh<1><<<dim3(RDIM / 128, TT / 128), 256, MM_SMEM_BYTES>>>(p_q, p_wr1, br1, p_h, RDIM, DQ);
    // lam + fused
    router_fused_kernel<<<TT, 256>>>(X, Wr2, br2);
    // k, v fused launch (fp16 outs)
    mmh_kv<<<dim3(2 * DKV / 128, TT / 128), 256, MM_SMEM_BYTES>>>(p_fused, p_wk, p_wv, p_k, p_v, DD);
    // RoPE: q gets softmax scale * log2e folded in; k plain
    rope_kernel<<<TT, 256>>>(p_q, DQ, NH, ATTN_SCALE * LOG2E);
    rope_kernel<<<TT, 256>>>(p_k, DKV, NKV, 1.0f);
    // V k-pair interleave for P@V B-operand
    vinterleave_kernel<<<(TT / 2) * (DKV / 4) / 256, 256>>>();
    // attention
    attn_kernel<<<dim3(TT / 64, NH / 2), 256, ATTN_SMEM_BYTES>>>();
    // out = attn @ Wo (fp32 out)
    mmh<0><<<dim3(DD / 128, TT / 128), 256, MM_SMEM_BYTES>>>(p_attn, p_wo, nullptr, out, DD, DQ);
}

// round 16
// speedup vs baseline: 1.5925x; 1.5074x over previous
#include <cuda_runtime.h>
#include <cuda_fp16.h>
#include <math.h>
#include <stdint.h>

#define TT 2048
#define DD 2048
#define NH 16
#define NKV 4
#define HDIM 128
#define DQ 2048    // NH*HD
#define DKV 512    // NKV*HD
#define RDIM 1024  // D/2
#define EMA_L 64
#define EMA_NC 32

#define BETA 0.9f
#define ALPHA 0.1f
#define ATTN_SCALE 0.08838834764831843f  // 1/sqrt(128)
#define LOG2E 1.4426950408889634f

// ------------------- scratch -------------------
__device__ float g_l2[TT * DD];
__device__ float g_carry[EMA_NC * DD];
__device__ float g_prefix[EMA_NC * DD];
__device__ double g_invfreq[64];
// fp16 activations
__device__ __half g_xr[TT * DD];
__device__ __half g_q[TT * DQ];
__device__ __half g_h[TT * RDIM];
__device__ __half g_fused[TT * DD];
__device__ __half g_k[TT * DKV];
__device__ __half g_v[TT * DKV];
__device__ __half g_attn[TT * DQ];
// fp16 weights, k-pair interleaved: half2[K/2][N]
__device__ __half g_wq[DD * DQ];
__device__ __half g_wk[DD * DKV];
__device__ __half g_wv[DD * DKV];
__device__ __half g_wo[DQ * DD];
__device__ __half g_wr1[DD * RDIM];

// ------------------- helpers -------------------
__device__ __forceinline__ uint32_t pack2(float a, float b) {
    __half2 h = __floats2half2_rn(a, b);
    return *(uint32_t*)&h;
}
__device__ __forceinline__ void mma16(float* c, const uint32_t* a, uint32_t b0, uint32_t b1) {
    asm volatile(
        "mma.sync.aligned.m16n8k16.row.col.f32.f16.f16.f32 "
        "{%0,%1,%2,%3}, {%4,%5,%6,%7}, {%8,%9}, {%0,%1,%2,%3};\n"
        : "+f"(c[0]), "+f"(c[1]), "+f"(c[2]), "+f"(c[3])
        : "r"(a[0]), "r"(a[1]), "r"(a[2]), "r"(a[3]), "r"(b0), "r"(b1));
}
__device__ __forceinline__ void ldmx4(uint32_t& r0, uint32_t& r1, uint32_t& r2, uint32_t& r3,
                                      uint32_t addr) {
    asm volatile("ldmatrix.sync.aligned.m8n8.x4.shared.b16 {%0,%1,%2,%3}, [%4];"
                 : "=r"(r0), "=r"(r1), "=r"(r2), "=r"(r3) : "r"(addr));
}
__device__ __forceinline__ void ldmx4t(uint32_t& r0, uint32_t& r1, uint32_t& r2, uint32_t& r3,
                                       uint32_t addr) {
    asm volatile("ldmatrix.sync.aligned.m8n8.x4.trans.shared.b16 {%0,%1,%2,%3}, [%4];"
                 : "=r"(r0), "=r"(r1), "=r"(r2), "=r"(r3) : "r"(addr));
}
__device__ __forceinline__ uint32_t smem_u32(const void* p) {
    uint32_t a;
    asm("{ .reg .u64 t; cvta.to.shared.u64 t, %1; cvt.u32.u64 %0, t; }" : "=r"(a) : "l"(p));
    return a;
}
__device__ __forceinline__ void cpasync16(uint32_t dst, const void* src) {
    asm volatile("cp.async.ca.shared.global [%0], [%1], 16;\n" :: "r"(dst), "l"(src));
}
#define CP_COMMIT() asm volatile("cp.async.commit_group;\n" ::: "memory")
#define CP_WAIT(N) asm volatile("cp.async.wait_group %0;\n" :: "n"(N) : "memory")

// fast exp2 (poly on FMA pipe); valid for x <= 0
__device__ __forceinline__ float fexp2(float x) {
    x = fmaxf(x, -126.0f);
    int ei = __float2int_rd(x);
    float f = x - (float)ei;
    float p = 1.535336188319500e-4f;
    p = fmaf(p, f, 1.339887440266574e-3f);
    p = fmaf(p, f, 9.618437357674640e-3f);
    p = fmaf(p, f, 5.550332471162809e-2f);
    p = fmaf(p, f, 2.402264791363012e-1f);
    p = fmaf(p, f, 6.931472028550421e-1f);
    p = fmaf(p, f, 1.0f);
    return p * __int_as_float((ei + 127) << 23);
}

// ------------------- RoPE frequency table -------------------
__global__ void freq_kernel() {
    int i = threadIdx.x;
    g_invfreq[i] = pow(10000.0, -(double)i / 64.0);
}

// ------------------- weight convert: fp32 [K,N] -> fp16 k-pair-interleaved half2[K/2][N]
__global__ __launch_bounds__(256) void wconv_kernel(const float* __restrict__ in,
                                                    __half* __restrict__ outh, int N) {
    __half2* out = (__half2*)outh;
    int idx = blockIdx.x * 256 + threadIdx.x;
    int perRow = N >> 2;
    int k2 = idx / perRow;
    int c = (idx - k2 * perRow) << 2;
    float4 a = *(const float4*)&in[(size_t)(2 * k2) * N + c];
    float4 b = *(const float4*)&in[(size_t)(2 * k2 + 1) * N + c];
    __half2 o0 = __floats2half2_rn(a.x, b.x);
    __half2 o1 = __floats2half2_rn(a.y, b.y);
    __half2 o2 = __floats2half2_rn(a.z, b.z);
    __half2 o3 = __floats2half2_rn(a.w, b.w);
    uint4 st;
    st.x = *(uint32_t*)&o0; st.y = *(uint32_t*)&o1;
    st.z = *(uint32_t*)&o2; st.w = *(uint32_t*)&o3;
    *(uint4*)&out[(size_t)k2 * N + c] = st;
}

// ------------------- EMA: 3-pass exact chunked scan; emits fp16 X_r --------------
__global__ __launch_bounds__(256) void ema_local_kernel(const float* __restrict__ X) {
    int gidx = blockIdx.x * 256 + threadIdx.x;
    int c = gidx >> 9;
    int d4 = (gidx & 511) << 2;
    float4 m = make_float4(0.f, 0.f, 0.f, 0.f);
    int t0 = c * EMA_L;
#pragma unroll 2
    for (int i = 0; i < EMA_L; i++) {
        size_t off = (size_t)(t0 + i) * DD + d4;
        float4 x = *(const float4*)&X[off];
        m.x = fmaf(BETA, m.x, ALPHA * x.x);
        m.y = fmaf(BETA, m.y, ALPHA * x.y);
        m.z = fmaf(BETA, m.z, ALPHA * x.z);
        m.w = fmaf(BETA, m.w, ALPHA * x.w);
        *(float4*)&g_l2[off] = m;
        __half2 h01 = __floats2half2_rn(x.x, x.y);
        __half2 h23 = __floats2half2_rn(x.z, x.w);
        uint2 st;
        st.x = *(uint32_t*)&h01; st.y = *(uint32_t*)&h23;
        *(uint2*)&g_xr[off] = st;
    }
    *(float4*)&g_carry[c * DD + d4] = m;
}

__global__ void ema_scan_kernel() {
    int d4 = (blockIdx.x * 256 + threadIdx.x) * 4;
    float bl = 1.f;
#pragma unroll
    for (int i = 0; i < EMA_L; i++) bl *= BETA;
    float4 m = make_float4(0.f, 0.f, 0.f, 0.f);
#pragma unroll
    for (int c = 0; c < EMA_NC; c++) {
        *(float4*)&g_prefix[c * DD + d4] = m;
        float4 cr = *(const float4*)&g_carry[c * DD + d4];
        m.x = fmaf(bl, m.x, cr.x);
        m.y = fmaf(bl, m.y, cr.y);
        m.z = fmaf(bl, m.z, cr.z);
        m.w = fmaf(bl, m.w, cr.w);
    }
}

__global__ __launch_bounds__(256) void ema_fix_kernel() {
    int gidx = blockIdx.x * 256 + threadIdx.x;
    int c = (gidx >> 9) + 1;
    int d4 = (gidx & 511) << 2;
    float4 p = *(const float4*)&g_prefix[c * DD + d4];
    float f = BETA;
    int t0 = c * EMA_L;
#pragma unroll 2
    for (int i = 0; i < EMA_L; i++) {
        size_t off = (size_t)(t0 + i) * DD + d4;
        float4 v = *(float4*)&g_l2[off];
        v.x = fmaf(f, p.x, v.x);
        v.y = fmaf(f, p.y, v.y);
        v.z = fmaf(f, p.z, v.z);
        v.w = fmaf(f, p.w, v.w);
        *(float4*)&g_l2[off] = v;
        f *= BETA;
    }
}

// ------------------- fp16 GEMM: 3-stage cp.async, m16n8k16 -------------------
#define AP2 20
#define BP2 132
#define ASZB (128 * AP2 * 4)
#define BSZB (16 * BP2 * 4)
#define STGB (ASZB + BSZB)
#define STGW (STGB / 4)
#define MM_SMEM_BYTES (3 * STGB)

__device__ __forceinline__ void mm_issue(uint32_t sbase, const __half* Ax,
                                         const __half2* Bx,
                                         const uint32_t* aOffs, const uint32_t* bOffs,
                                         int N, int K) {
#pragma unroll
    for (int u = 0; u < 2; u++) cpasync16(sbase + aOffs[u], Ax + (size_t)(64 * u) * K);
#pragma unroll
    for (int u = 0; u < 2; u++) cpasync16(sbase + bOffs[u], Bx + (size_t)(8 * u) * N);
    CP_COMMIT();
}

// EPI: 0 = fp32 store, 1 = bias+silu fp16 store, 2 = fp16 store
template <int EPI>
__device__ __forceinline__ void mm_core(
    const __half* __restrict__ A, const __half* __restrict__ Bh,
    const float* __restrict__ bias, void* __restrict__ C,
    int N, int K, int bx, int by, uint32_t* sm)
{
    const __half2* B2 = (const __half2*)Bh;
    const int tid = threadIdx.x;
    const int aRow = tid >> 2;
    const int aSeg = tid & 3;
    const int bRow = tid >> 5;
    const int bSeg = tid & 31;

    const __half* Asrc = A + (size_t)(by * 128 + aRow) * K + aSeg * 8;
    const __half2* Bsrc = B2 + (size_t)bRow * N + bx * 128 + bSeg * 4;

    const uint32_t sb = smem_u32(sm);
    uint32_t aOffs[2], bOffs[2];
#pragma unroll
    for (int u = 0; u < 2; u++) {
        aOffs[u] = (uint32_t)((aRow + 64 * u) * (AP2 * 4) + aSeg * 16);
        bOffs[u] = (uint32_t)(ASZB + (bRow + 8 * u) * (BP2 * 4) + bSeg * 16);
    }

    const int lane = tid & 31;
    const int wid = tid >> 5;
    const int m0 = (wid >> 2) * 64;
    const int n0 = (wid & 3) * 32;
    const int g = lane >> 2;
    const int q = lane & 3;

    const int iters = K / 32;
    mm_issue(sb, Asrc, Bsrc, aOffs, bOffs, N, K);
    mm_issue(sb + STGB, Asrc + 32, Bsrc + (size_t)16 * N, aOffs, bOffs, N, K);

    float acc[4][4][4];
#pragma unroll
    for (int i = 0; i < 4; i++)
#pragma unroll
        for (int j = 0; j < 4; j++)
#pragma unroll
            for (int c = 0; c < 4; c++) acc[i][j][c] = 0.f;

    for (int it = 0; it < iters; it++) {
        CP_WAIT(1);
        __syncthreads();

        const int nt = it + 2;
        if (nt < iters) {
            mm_issue(sb + (uint32_t)((nt % 3) * STGB),
                     Asrc + (size_t)nt * 32, Bsrc + (size_t)nt * 16 * N,
                     aOffs, bOffs, N, K);
        } else {
            CP_COMMIT();
        }

        const uint32_t* As = sm + (it % 3) * STGW;
        const uint32_t* Bs = As + ASZB / 4;

#pragma unroll
        for (int kk = 0; kk < 2; kk++) {
            const int ks = kk * 8;
            uint32_t af[4][4], bf[4][2];
#pragma unroll
            for (int i = 0; i < 4; i++) {
                const int mr = m0 + i * 16 + g;
                af[i][0] = As[mr * AP2 + ks + q];
                af[i][1] = As[(mr + 8) * AP2 + ks + q];
                af[i][2] = As[mr * AP2 + ks + q + 4];
                af[i][3] = As[(mr + 8) * AP2 + ks + q + 4];
            }
#pragma unroll
            for (int j = 0; j < 4; j++) {
                const int nc = n0 + j * 8 + g;
                bf[j][0] = Bs[(ks + q) * BP2 + nc];
                bf[j][1] = Bs[(ks + q + 4) * BP2 + nc];
            }
#pragma unroll
            for (int i = 0; i < 4; i++)
#pragma unroll
                for (int j = 0; j < 4; j++)
                    mma16(acc[i][j], af[i], bf[j][0], bf[j][1]);
        }
    }

#pragma unroll
    for (int i = 0; i < 4; i++) {
#pragma unroll
        for (int j = 0; j < 4; j++) {
            const int row0 = by * 128 + m0 + i * 16 + g;
            const int col = bx * 128 + n0 + j * 8 + 2 * q;
            float v0 = acc[i][j][0], v1 = acc[i][j][1];
            float v2 = acc[i][j][2], v3 = acc[i][j][3];
            if (EPI == 1) {
                float b0v = bias[col], b1v = bias[col + 1];
                v0 += b0v; v1 += b1v; v2 += b0v; v3 += b1v;
                v0 = v0 / (1.f + __expf(-v0));
                v1 = v1 / (1.f + __expf(-v1));
                v2 = v2 / (1.f + __expf(-v2));
                v3 = v3 / (1.f + __expf(-v3));
            }
            if (EPI == 0) {
                float* Cf = (float*)C;
                *(float2*)&Cf[(size_t)row0 * N + col] = make_float2(v0, v1);
                *(float2*)&Cf[(size_t)(row0 + 8) * N + col] = make_float2(v2, v3);
            } else {
                __half* Ch = (__half*)C;
                __half2 h0 = __floats2half2_rn(v0, v1);
                __half2 h1 = __floats2half2_rn(v2, v3);
                *(__half2*)&Ch[(size_t)row0 * N + col] = h0;
                *(__half2*)&Ch[(size_t)(row0 + 8) * N + col] = h1;
            }
        }
    }
}

template <int EPI>
__global__ __launch_bounds__(256, 2) void mmh(
    const __half* __restrict__ A, const __half* __restrict__ B,
    const float* __restrict__ bias, void* __restrict__ C, int N, int K)
{
    extern __shared__ uint32_t sm[];
    mm_core<EPI>(A, B, bias, C, N, K, blockIdx.x, blockIdx.y, sm);
}

__global__ __launch_bounds__(256, 2) void mmh_kv(
    const __half* __restrict__ A,
    const __half* __restrict__ B0, const __half* __restrict__ B1,
    __half* __restrict__ C0, __half* __restrict__ C1, int K)
{
    extern __shared__ uint32_t sm[];
    const int sel = blockIdx.x >> 2;
    mm_core<2>(A, sel ? B1 : B0, nullptr, sel ? (void*)C1 : (void*)C0,
               DKV, K, blockIdx.x & 3, blockIdx.y, sm);
}

// ------------------- router (reads fp16 h; stores fp16 fused) -------------------
__global__ __launch_bounds__(256) void router_fused_kernel(
    const float* __restrict__ X, const float* __restrict__ Wr2, const float* __restrict__ br2)
{
    const int t = blockIdx.x;
    const int tid = threadIdx.x;
    __shared__ float red[512];
    __shared__ float lam[2];

    float s0 = 0.f, s1 = 0.f;
    for (int j = tid; j < RDIM; j += 256) {
        float hv = __half2float(g_h[t * RDIM + j]);
        s0 = fmaf(hv, Wr2[2 * j + 0], s0);
        s1 = fmaf(hv, Wr2[2 * j + 1], s1);
    }
    red[tid] = s0;
    red[256 + tid] = s1;
    __syncthreads();
    for (int off = 128; off > 0; off >>= 1) {
        if (tid < off) {
            red[tid] += red[tid + off];
            red[256 + tid] += red[256 + tid + off];
        }
        __syncthreads();
    }
    if (tid == 0) {
        float a = red[0] + br2[0];
        float b = red[256] + br2[1];
        float mx = fmaxf(a, b);
        float e0 = __expf(a - mx), e1 = __expf(b - mx);
        float inv = 1.f / (e0 + e1);
        lam[0] = e0 * inv;
        lam[1] = e1 * inv;
    }
    __syncthreads();
    float l0 = lam[0], l1 = lam[1];
    for (int c = tid * 4; c < DD; c += 1024) {
        float4 x4 = *(const float4*)&X[t * DD + c];
        float4 m4 = *(const float4*)&g_l2[t * DD + c];
        __half2 h01 = __floats2half2_rn(fmaf(l0, x4.x, l1 * m4.x),
                                        fmaf(l0, x4.y, l1 * m4.y));
        __half2 h23 = __floats2half2_rn(fmaf(l0, x4.z, l1 * m4.z),
                                        fmaf(l0, x4.w, l1 * m4.w));
        uint2 st;
        st.x = *(uint32_t*)&h01; st.y = *(uint32_t*)&h23;
        *(uint2*)&g_fused[t * DD + c] = st;
    }
}

// ------------------- RoPE (merged q+k; fp16 in place) -------------------
__global__ __launch_bounds__(256) void rope2_kernel(__half* __restrict__ Q,
                                                    __half* __restrict__ Kp,
                                                    float qscale) {
    const int t = blockIdx.x;
    const int which = blockIdx.y;
    const int tid = threadIdx.x;
    const int hh = tid >> 6;
    const int i = tid & 63;
    const double inv = g_invfreq[i];
    const float ang = (float)((double)t * inv);
    float s, c;
    sincosf(ang, &s, &c);
    __half* M = which ? Kp : Q;
    const int rowStride = which ? DKV : DQ;
    const int nheads = which ? NKV : NH;
    const float scale = which ? 1.0f : qscale;
    for (int head = hh; head < nheads; head += 4) {
        const int base = t * rowStride + head * HDIM;
        float x1 = __half2float(M[base + i]);
        float x2 = __half2float(M[base + 64 + i]);
        float o1 = (x1 * c - x2 * s) * scale;
        float o2 = fmaf(x2, c, x1 * s) * scale;
        M[base + i] = __float2half_rn(o1);
        M[base + 64 + i] = __float2half_rn(o2);
    }
}

// ------------------- flash attention (causal GQA, fp16 mma + ldmatrix) -------------
// grid (32, 8): 64 q-rows x 2 heads (same KV group). 256 threads (8 warps).
// All tiles plain row-major: 64 rows x 128 halfs, 272B pitch (68 words).
#define RPITCH 272
#define KP2 68                       // pitch in half2/words
#define SLOT_B (64 * RPITCH)         // 17408
#define ATTN_SMEM_BYTES (4 * SLOT_B) // 69632

__global__ __launch_bounds__(256) void attn_kernel() {
    extern __shared__ uint32_t smw[];

    const int qt = (int)gridDim.x - 1 - (int)blockIdx.x;   // heavy first
    const int hp2 = blockIdx.y;
    const int tid = threadIdx.x;
    const int lane = tid & 31;
    const int wid = tid >> 5;
    const int hp = wid >> 2;
    const int ws = wid & 3;
    const int h = 2 * hp2 + hp;
    const int kvh = hp2 >> 1;
    const int g = lane >> 2;
    const int q = lane & 3;
    const int m0 = ws * 16;
    const int q0 = qt * 64;

    const uint32_t sb = smem_u32(smw);

    // lane-constant ldmatrix offsets
    const uint32_t kOff = (uint32_t)(((lane & 7) + 8 * (lane >> 4)) * RPITCH
                                     + 16 * ((lane >> 3) & 1));
    const uint32_t vOff = (uint32_t)(((lane & 7) + 8 * ((lane >> 3) & 1)) * RPITCH
                                     + 16 * (lane >> 4));

    // ---- stage Q of both heads into slots 0,1 ----
#pragma unroll
    for (int u = 0; u < 4; u++) {
        int linear = u * 256 + tid;           // 0..1023
        int r = linear >> 4;
        int s = linear & 15;
        cpasync16(sb + (uint32_t)(r * RPITCH + s * 16),
                  &g_q[(size_t)(q0 + r) * DQ + (2 * hp2) * HDIM + s * 8]);
        cpasync16(sb + (uint32_t)(SLOT_B + r * RPITCH + s * 16),
                  &g_q[(size_t)(q0 + r) * DQ + (2 * hp2 + 1) * HDIM + s * 8]);
    }
    CP_COMMIT();
    CP_WAIT(0);
    __syncthreads();

    uint32_t qf[8][4];
    {
        const uint32_t* Qb = smw + (hp ? SLOT_B / 4 : 0);
#pragma unroll
        for (int kk = 0; kk < 8; kk++) {
            const int base = (m0 + g) * KP2 + kk * 8 + q;
            qf[kk][0] = Qb[base];
            qf[kk][1] = Qb[base + 8 * KP2];
            qf[kk][2] = Qb[base + 4];
            qf[kk][3] = Qb[base + 8 * KP2 + 4];
        }
    }
    __syncthreads();

    float oacc[16][4];
#pragma unroll
    for (int n = 0; n < 16; n++)
#pragma unroll
        for (int c = 0; c < 4; c++) oacc[n][c] = 0.f;
    float mrow[2] = {-1e30f, -1e30f};
    float lrow[2] = {0.f, 0.f};

    // prefetch tile 0 into slots 0 (K), 1 (V)
    {
#pragma unroll
        for (int u = 0; u < 4; u++) {
            int linear = u * 256 + tid;
            int r = linear >> 4, s = linear & 15;
            cpasync16(sb + (uint32_t)(r * RPITCH + s * 16),
                      &g_k[(size_t)r * DKV + kvh * HDIM + s * 8]);
            cpasync16(sb + (uint32_t)(SLOT_B + r * RPITCH + s * 16),
                      &g_v[(size_t)r * DKV + kvh * HDIM + s * 8]);
        }
        CP_COMMIT();
    }

    for (int kt = 0; kt <= qt; kt++) {
        const int st = kt & 1;
        if (kt < qt) {
            const int k0n = (kt + 1) * 64;
            const uint32_t basew = (uint32_t)((st ^ 1) * 2 * SLOT_B);
#pragma unroll
            for (int u = 0; u < 4; u++) {
                int linear = u * 256 + tid;
                int r = linear >> 4, s = linear & 15;
                cpasync16(sb + basew + (uint32_t)(r * RPITCH + s * 16),
                          &g_k[(size_t)(k0n + r) * DKV + kvh * HDIM + s * 8]);
                cpasync16(sb + basew + SLOT_B + (uint32_t)(r * RPITCH + s * 16),
                          &g_v[(size_t)(k0n + r) * DKV + kvh * HDIM + s * 8]);
            }
            CP_COMMIT();
            CP_WAIT(1);
        } else {
            CP_WAIT(0);
        }
        __syncthreads();

        const uint32_t Ka = sb + (uint32_t)(st * 2 * SLOT_B) + kOff;
        const uint32_t Va = sb + (uint32_t)(st * 2 * SLOT_B + SLOT_B) + vOff;

        // ---- S = Q @ K^T : 16 x 64 per warp (K b-frags via ldmatrix) ----
        float sacc[8][4];
#pragma unroll
        for (int n = 0; n < 8; n++)
#pragma unroll
            for (int c = 0; c < 4; c++) sacc[n][c] = 0.f;
#pragma unroll
        for (int kk = 0; kk < 8; kk++) {
#pragma unroll
            for (int p = 0; p < 4; p++) {
                uint32_t r0, r1, r2, r3;
                ldmx4(r0, r1, r2, r3, Ka + (uint32_t)(p * 16 * RPITCH + kk * 32));
                mma16(sacc[2 * p], qf[kk], r0, r1);
                mma16(sacc[2 * p + 1], qf[kk], r2, r3);
            }
        }

        // ---- causal mask (diagonal tile) ----
        if (kt == qt) {
#pragma unroll
            for (int n = 0; n < 8; n++) {
                const int col0 = n * 8 + 2 * q;
                const int rA = m0 + g, rB = m0 + g + 8;
                if (col0 > rA) sacc[n][0] = -1e30f;
                if (col0 + 1 > rA) sacc[n][1] = -1e30f;
                if (col0 > rB) sacc[n][2] = -1e30f;
                if (col0 + 1 > rB) sacc[n][3] = -1e30f;
            }
        }

        // ---- online softmax (base-2) ----
        float mx0 = -1e30f, mx1 = -1e30f;
#pragma unroll
        for (int n = 0; n < 8; n++) {
            mx0 = fmaxf(mx0, fmaxf(sacc[n][0], sacc[n][1]));
            mx1 = fmaxf(mx1, fmaxf(sacc[n][2], sacc[n][3]));
        }
        mx0 = fmaxf(mx0, __shfl_xor_sync(0xffffffffu, mx0, 1));
        mx0 = fmaxf(mx0, __shfl_xor_sync(0xffffffffu, mx0, 2));
        mx1 = fmaxf(mx1, __shfl_xor_sync(0xffffffffu, mx1, 1));
        mx1 = fmaxf(mx1, __shfl_xor_sync(0xffffffffu, mx1, 2));

        const float nm0 = fmaxf(mrow[0], mx0);
        const float nm1 = fmaxf(mrow[1], mx1);
        const float corr0 = fexp2(mrow[0] - nm0);
        const float corr1 = fexp2(mrow[1] - nm1);
        float rs0 = 0.f, rs1 = 0.f;
#pragma unroll
        for (int n = 0; n < 8; n++) {
            sacc[n][0] = fexp2(sacc[n][0] - nm0);
            sacc[n][1] = fexp2(sacc[n][1] - nm0);
            sacc[n][2] = fexp2(sacc[n][2] - nm1);
            sacc[n][3] = fexp2(sacc[n][3] - nm1);
            rs0 += sacc[n][0] + sacc[n][1];
            rs1 += sacc[n][2] + sacc[n][3];
        }
        rs0 += __shfl_xor_sync(0xffffffffu, rs0, 1);
        rs0 += __shfl_xor_sync(0xffffffffu, rs0, 2);
        rs1 += __shfl_xor_sync(0xffffffffu, rs1, 1);
        rs1 += __shfl_xor_sync(0xffffffffu, rs1, 2);
        lrow[0] = lrow[0] * corr0 + rs0;
        lrow[1] = lrow[1] * corr1 + rs1;
        mrow[0] = nm0;
        mrow[1] = nm1;
#pragma unroll
        for (int n = 0; n < 16; n++) {
            oacc[n][0] *= corr0;
            oacc[n][1] *= corr0;
            oacc[n][2] *= corr1;
            oacc[n][3] *= corr1;
        }

        // ---- O += P @ V : P A-frag from sacc; V b-frags via ldmatrix.trans ----
#pragma unroll
        for (int kk = 0; kk < 4; kk++) {
            uint32_t pa[4];
            pa[0] = pack2(sacc[2 * kk][0], sacc[2 * kk][1]);
            pa[1] = pack2(sacc[2 * kk][2], sacc[2 * kk][3]);
            pa[2] = pack2(sacc[2 * kk + 1][0], sacc[2 * kk + 1][1]);
            pa[3] = pack2(sacc[2 * kk + 1][2], sacc[2 * kk + 1][3]);
            const uint32_t vrow = Va + (uint32_t)(kk * 16 * RPITCH);
#pragma unroll
            for (int p = 0; p < 8; p++) {
                uint32_t r0, r1, r2, r3;
                ldmx4t(r0, r1, r2, r3, vrow + (uint32_t)(p * 32));
                mma16(oacc[2 * p], pa, r0, r1);
                mma16(oacc[2 * p + 1], pa, r2, r3);
            }
        }
        __syncthreads();
    }

    // ---- write O (fp16: A operand of the Wo GEMM) ----
    const float inv0 = 1.f / lrow[0];
    const float inv1 = 1.f / lrow[1];
    const int rowA = q0 + m0 + g;
    const int rowB = rowA + 8;
#pragma unroll
    for (int n = 0; n < 16; n++) {
        const int col = h * HDIM + n * 8 + 2 * q;
        __half2 h0 = __floats2half2_rn(oacc[n][0] * inv0, oacc[n][1] * inv0);
        __half2 h1 = __floats2half2_rn(oacc[n][2] * inv1, oacc[n][3] * inv1);
        *(__half2*)&g_attn[(size_t)rowA * DQ + col] = h0;
        *(__half2*)&g_attn[(size_t)rowB * DQ + col] = h1;
    }
}

// ------------------- host launch -------------------
extern "C" void kernel_launch(void* const* d_in, const int* in_sizes, int n_in,
                              void* d_out, int out_size) {
    const float* X   = (const float*)d_in[0];
    const float* Wq  = (const float*)d_in[1];
    const float* Wk  = (const float*)d_in[2];
    const float* Wv  = (const float*)d_in[3];
    const float* Wo  = (const float*)d_in[4];
    const float* Wr1 = (const float*)d_in[5];
    const float* br1 = (const float*)d_in[6];
    const float* Wr2 = (const float*)d_in[7];
    const float* br2 = (const float*)d_in[8];
    float* out = (float*)d_out;

    __half *p_q, *p_h, *p_fused, *p_k, *p_v, *p_attn, *p_xr;
    __half *p_wq, *p_wk, *p_wv, *p_wo, *p_wr1;
    cudaGetSymbolAddress((void**)&p_q, g_q);
    cudaGetSymbolAddress((void**)&p_h, g_h);
    cudaGetSymbolAddress((void**)&p_fused, g_fused);
    cudaGetSymbolAddress((void**)&p_k, g_k);
    cudaGetSymbolAddress((void**)&p_v, g_v);
    cudaGetSymbolAddress((void**)&p_attn, g_attn);
    cudaGetSymbolAddress((void**)&p_xr, g_xr);
    cudaGetSymbolAddress((void**)&p_wq, g_wq);
    cudaGetSymbolAddress((void**)&p_wk, g_wk);
    cudaGetSymbolAddress((void**)&p_wv, g_wv);
    cudaGetSymbolAddress((void**)&p_wo, g_wo);
    cudaGetSymbolAddress((void**)&p_wr1, g_wr1);

    cudaFuncSetAttribute(attn_kernel, cudaFuncAttributeMaxDynamicSharedMemorySize, ATTN_SMEM_BYTES);
    cudaFuncSetAttribute(mmh<0>, cudaFuncAttributeMaxDynamicSharedMemorySize, MM_SMEM_BYTES);
    cudaFuncSetAttribute(mmh<1>, cudaFuncAttributeMaxDynamicSharedMemorySize, MM_SMEM_BYTES);
    cudaFuncSetAttribute(mmh<2>, cudaFuncAttributeMaxDynamicSharedMemorySize, MM_SMEM_BYTES);
    cudaFuncSetAttribute(mmh_kv, cudaFuncAttributeMaxDynamicSharedMemorySize, MM_SMEM_BYTES);

    // freq table + weight convert (fp16, k-pair interleaved)
    freq_kernel<<<1, 64>>>();
    wconv_kernel<<<(DD / 2) * (DQ / 4) / 256, 256>>>(Wq, p_wq, DQ);
    wconv_kernel<<<(DD / 2) * (DKV / 4) / 256, 256>>>(Wk, p_wk, DKV);
    wconv_kernel<<<(DD / 2) * (DKV / 4) / 256, 256>>>(Wv, p_wv, DKV);
    wconv_kernel<<<(DQ / 2) * (DD / 4) / 256, 256>>>(Wo, p_wo, DD);
    wconv_kernel<<<(DD / 2) * (RDIM / 4) / 256, 256>>>(Wr1, p_wr1, RDIM);

    // EMA (also emits fp16 X_r)
    ema_local_kernel<<<(EMA_NC * DD / 4) / 256, 256>>>(X);
    ema_scan_kernel<<<2, 256>>>();
    ema_fix_kernel<<<((EMA_NC - 1) * DD / 4) / 256, 256>>>();

    // q = X @ Wq (fp16 out, pre-RoPE; feeds Wr1)
    mmh<2><<<dim3(DQ / 128, TT / 128), 256, MM_SMEM_BYTES>>>(p_xr, p_wq, nullptr, p_q, DQ, DD);
    // h = silu(q @ Wr1 + br1)
    mmh<1><<<dim3(RDIM / 128, TT / 128), 256, MM_SMEM_BYTES>>>(p_q, p_wr1, br1, p_h, RDIM, DQ);
    // lam + fused
    router_fused_kernel<<<TT, 256>>>(X, Wr2, br2);
    // k, v fused launch (fp16 outs)
    mmh_kv<<<dim3(2 * DKV / 128, TT / 128), 256, MM_SMEM_BYTES>>>(p_fused, p_wk, p_wv, p_k, p_v, DD);
    // RoPE merged: y=0 -> q (scale*log2e), y=1 -> k
    rope2_kernel<<<dim3(TT, 2), 256>>>(p_q, p_k, ATTN_SCALE * LOG2E);
    // attention
    attn_kernel<<<dim3(TT / 64, NH / 2), 256, ATTN_SMEM_BYTES>>>();
    // out = attn @ Wo (fp32 out)
    mmh<0><<<dim3(DD / 128, TT / 128), 256, MM_SMEM_BYTES>>>(p_attn, p_wo, nullptr, out, DD, DQ);
}